// round 6
// baseline (speedup 1.0000x reference)
#include <cuda_runtime.h>
#include <math.h>

#define BB 32
#define TT 256
#define FF 2048
#define KK 16
#define NCC 10
#define SLICES 2        // CTAs per row
#define NTHR 256        // 8 warps

__device__ float g_part[2 * BB][SLICES];
__device__ float g_vls[2 * BB];
__device__ unsigned int g_count = 0;

__global__ void fused_kernel(
    const float* __restrict__ abn_fm,
    const float* __restrict__ nor_fm,
    const float* __restrict__ abn_ft,
    const float* __restrict__ nor_ft,
    const float* __restrict__ abn_sls,
    const float* __restrict__ nor_sls,
    const float* __restrict__ abn_dm,
    const float* __restrict__ nor_dm,
    const float* __restrict__ label,
    float* __restrict__ out)
{
    const int bid   = blockIdx.x;          // 0..127
    const int row   = bid >> 1;            // 0..63
    const int slice = bid & (SLICES - 1);  // 0..1
    const int b     = row & (BB - 1);
    const bool is_abn = (row < BB);

    const float* fm  = is_abn ? abn_fm  : nor_fm;
    const float* dm  = is_abn ? abn_dm  : nor_dm;
    const float* sls = is_abn ? abn_sls : nor_sls;
    const float* ft  = (is_abn ? abn_ft : nor_ft)
                     + (size_t)(NCC - 1) * BB * TT * FF + (size_t)b * TT * FF;

    const int tid  = threadIdx.x;
    const int wid  = tid >> 5;
    const int lane = tid & 31;
    const bool vls_warp = (slice == 0 && wid == 0);

    // ---- prefetch sls row into registers (vls warp only; overlaps top-K) ----
    float sv[8];
    if (vls_warp) {
        #pragma unroll
        for (int j = 0; j < 8; j++) sv[j] = sls[b * TT + j * 32 + lane];
    }

    // ---- drop values: lane l, slot j -> t = j*32 + l ; key = float bits ----
    unsigned int key[8];
    #pragma unroll
    for (int j = 0; j < 8; j++) {
        int t = j * 32 + lane;
        float v = fm[b * TT + t] * dm[b * TT + t];
        key[j] = __float_as_uint(v);
    }

    // ---- per-warp redundant top-16 via REDUX; round-k gather load issued
    //      into its OWN register quad v[k] (no consumer until after the loop),
    //      so load latency drains behind later rounds' ALU chain ----
    const float4* ft4 = (const float4*)ft;
    const int f4 = slice * (FF / 4 / SLICES) + tid;
    float4 v[KK];
    unsigned int myidx = 0;      // lane k holds selected index of round k

    #pragma unroll
    for (int k = 0; k < KK; k++) {
        unsigned int m = key[0];
        #pragma unroll
        for (int j = 1; j < 8; j++) m = max(m, key[j]);
        m = __reduce_max_sync(0xFFFFFFFFu, m);
        unsigned int cand = 0xFFFFFFFFu;
        #pragma unroll
        for (int j = 0; j < 8; j++)
            if (key[j] == m) cand = min(cand, (unsigned int)(j * 32 + lane));
        cand = __reduce_min_sync(0xFFFFFFFFu, cand);
        if (lane == k) myidx = cand;
        #pragma unroll
        for (int j = 0; j < 8; j++)
            if (key[j] == m && (unsigned int)(j * 32 + lane) == cand) key[j] = 0u;

        v[k] = ft4[(size_t)cand * (FF / 4) + f4];   // issue, don't consume
    }

    // ---- sls mean over selected: value shuffled from prefetched regs ----
    if (vls_warp) {
        int src  = (int)(myidx & 31u);
        int slot = (int)(myidx >> 5);
        float val = 0.0f;
        #pragma unroll
        for (int j = 0; j < 8; j++) {
            float t = __shfl_sync(0xFFFFFFFFu, sv[j], src);
            if (j == slot) val = t;
        }
        if (lane >= KK) val = 0.0f;
        #pragma unroll
        for (int off = 16; off > 0; off >>= 1)
            val += __shfl_xor_sync(0xFFFFFFFFu, val, off);
        if (lane == 0) g_vls[row] = val * (1.0f / KK);
    }

    // ---- deferred accumulation (loads mostly complete by now) ----
    float4 a0 = make_float4(0.f, 0.f, 0.f, 0.f);
    float4 a1 = make_float4(0.f, 0.f, 0.f, 0.f);
    #pragma unroll
    for (int k = 0; k < KK; k += 2) {
        a0.x += v[k].x;   a0.y += v[k].y;   a0.z += v[k].z;   a0.w += v[k].w;
        a1.x += v[k+1].x; a1.y += v[k+1].y; a1.z += v[k+1].z; a1.w += v[k+1].w;
    }
    a0.x += a1.x; a0.y += a1.y; a0.z += a1.z; a0.w += a1.w;
    float local = a0.x * a0.x + a0.y * a0.y + a0.z * a0.z + a0.w * a0.w;

    // ---- block reduce -> partial sum of squares ----
    __shared__ float swarp[8];
    __shared__ unsigned int s_last;
    #pragma unroll
    for (int off = 16; off > 0; off >>= 1)
        local += __shfl_xor_sync(0xFFFFFFFFu, local, off);
    if (lane == 0) swarp[wid] = local;
    __syncthreads();

    if (tid == 0) {
        float tot = 0.0f;
        #pragma unroll
        for (int w = 0; w < 8; w++) tot += swarp[w];
        g_part[row][slice] = tot;
        __threadfence();
        s_last = (atomicAdd(&g_count, 1u) == 2u * BB * SLICES - 1u) ? 1u : 0u;
    }
    __syncthreads();

    // ---- last block finalizes ----
    if (s_last) {
        __threadfence();
        __shared__ float s_rt[64];
        __shared__ float s_bce[64];

        if (tid < 64) {
            float rt = 0.0f;
            if (tid < BB) {
                float sa = __ldcg(&g_part[tid][0])      + __ldcg(&g_part[tid][1]);
                float sn = __ldcg(&g_part[BB + tid][0]) + __ldcg(&g_part[BB + tid][1]);
                float la = fabsf(100.0f - sqrtf(sa) * (1.0f / KK));
                float ln = sqrtf(sn) * (1.0f / KK);
                float l = la + ln;
                rt = l * l;
            }
            // vls = concat([vls_norm, vls_abn]); norm rows are 32..63
            float vv = (tid < BB) ? __ldcg(&g_vls[BB + tid]) : __ldcg(&g_vls[tid - BB]);
            float lab = label[tid];
            float logp   = fmaxf(logf(vv),    -100.0f);
            float log1mp = fmaxf(log1pf(-vv), -100.0f);
            s_rt[tid]  = rt;
            s_bce[tid] = lab * logp + (1.0f - lab) * log1mp;
        }
        __syncthreads();
        for (int s = 32; s > 0; s >>= 1) {
            if (tid < s) { s_rt[tid] += s_rt[tid + s]; s_bce[tid] += s_bce[tid + s]; }
            __syncthreads();
        }
        if (tid == 0) {
            out[0] = 1e-4f * (s_rt[0] * (1.0f / BB));
            out[1] = -s_bce[0] * (1.0f / 64.0f);
            g_count = 0;   // reset for next graph replay
        }
    }
}

extern "C" void kernel_launch(void* const* d_in, const int* in_sizes, int n_in,
                              void* d_out, int out_size)
{
    const float* abnr_fmagn = (const float*)d_in[0];
    const float* norm_fmagn = (const float*)d_in[1];
    const float* abnr_feats = (const float*)d_in[2];
    const float* norm_feats = (const float*)d_in[3];
    const float* abnr_sls   = (const float*)d_in[4];
    const float* norm_sls   = (const float*)d_in[5];
    const float* label      = (const float*)d_in[6];
    const float* drop_abn   = (const float*)d_in[7];
    const float* drop_norm  = (const float*)d_in[8];

    fused_kernel<<<2 * BB * SLICES, NTHR>>>(abnr_fmagn, norm_fmagn,
                                            abnr_feats, norm_feats,
                                            abnr_sls, norm_sls,
                                            drop_abn, drop_norm,
                                            label, (float*)d_out);
}

// round 7
// speedup vs baseline: 1.0352x; 1.0352x over previous
#include <cuda_runtime.h>
#include <math.h>

#define BB 32
#define TT 256
#define FF 2048
#define KK 16
#define NCC 10
#define SLICES 2        // CTAs per row
#define NTHR 256        // 8 warps
#define NL1 16          // level-1 arrival counters

__device__ float g_part[2 * BB][SLICES];
__device__ float g_vls[2 * BB];
__device__ unsigned int g_cnt1[NL1][32];   // 128B stride -> distinct LTS addresses
__device__ unsigned int g_cnt2 = 0;

__global__ void fused_kernel(
    const float* __restrict__ abn_fm,
    const float* __restrict__ nor_fm,
    const float* __restrict__ abn_ft,
    const float* __restrict__ nor_ft,
    const float* __restrict__ abn_sls,
    const float* __restrict__ nor_sls,
    const float* __restrict__ abn_dm,
    const float* __restrict__ nor_dm,
    const float* __restrict__ label,
    float* __restrict__ out)
{
    const int bid   = blockIdx.x;          // 0..127
    const int row   = bid >> 1;            // 0..63
    const int slice = bid & (SLICES - 1);  // 0..1
    const int b     = row & (BB - 1);
    const bool is_abn = (row < BB);

    const float* fm  = is_abn ? abn_fm  : nor_fm;
    const float* dm  = is_abn ? abn_dm  : nor_dm;
    const float* sls = is_abn ? abn_sls : nor_sls;
    const float* ft  = (is_abn ? abn_ft : nor_ft)
                     + (size_t)(NCC - 1) * BB * TT * FF + (size_t)b * TT * FF;

    const int tid  = threadIdx.x;
    const int wid  = tid >> 5;
    const int lane = tid & 31;
    const bool vls_warp = (slice == 0 && wid == 0);

    // ---- prefetch sls row into registers (vls warp only; overlaps top-K) ----
    float sv[8];
    if (vls_warp) {
        #pragma unroll
        for (int j = 0; j < 8; j++) sv[j] = sls[b * TT + j * 32 + lane];
    }

    // ---- packed keys: top 24 bits of float(v>=0) | (255 - t) in low byte.
    //      Distinct keys; zeros rank below all normals; among equal-truncated
    //      values smaller t wins (reference tie-break). ----
    unsigned int key[8];
    #pragma unroll
    for (int j = 0; j < 8; j++) {
        int t = j * 32 + lane;
        float v = fm[b * TT + t] * dm[b * TT + t];
        key[j] = (__float_as_uint(v) & 0xFFFFFF00u) | (255u - (unsigned int)t);
    }

    // ---- per-warp redundant top-16: ONE REDUX per round; index from low byte.
    //      Gather load issued into its own quad v[k], consumed after loop. ----
    const float4* ft4 = (const float4*)ft;
    const int f4 = slice * (FF / 4 / SLICES) + tid;
    float4 v[KK];
    unsigned int myidx = 0;      // lane k holds selected index of round k

    #pragma unroll
    for (int k = 0; k < KK; k++) {
        unsigned int m = key[0];
        #pragma unroll
        for (int j = 1; j < 8; j++) m = max(m, key[j]);
        m = __reduce_max_sync(0xFFFFFFFFu, m);
        unsigned int cand = 255u - (m & 0xFFu);   // uniform across warp
        if (lane == k) myidx = cand;
        #pragma unroll
        for (int j = 0; j < 8; j++)
            if (key[j] == m) key[j] = 0u;         // unique match

        v[k] = ft4[(size_t)cand * (FF / 4) + f4]; // issue, don't consume
    }

    // ---- sls mean over selected: value shuffled from prefetched regs ----
    if (vls_warp) {
        int src  = (int)(myidx & 31u);
        int slot = (int)(myidx >> 5);
        float val = 0.0f;
        #pragma unroll
        for (int j = 0; j < 8; j++) {
            float t = __shfl_sync(0xFFFFFFFFu, sv[j], src);
            if (j == slot) val = t;
        }
        if (lane >= KK) val = 0.0f;
        #pragma unroll
        for (int off = 16; off > 0; off >>= 1)
            val += __shfl_xor_sync(0xFFFFFFFFu, val, off);
        if (lane == 0) g_vls[row] = val * (1.0f / KK);
    }

    // ---- deferred accumulation ----
    float4 a0 = make_float4(0.f, 0.f, 0.f, 0.f);
    float4 a1 = make_float4(0.f, 0.f, 0.f, 0.f);
    #pragma unroll
    for (int k = 0; k < KK; k += 2) {
        a0.x += v[k].x;   a0.y += v[k].y;   a0.z += v[k].z;   a0.w += v[k].w;
        a1.x += v[k+1].x; a1.y += v[k+1].y; a1.z += v[k+1].z; a1.w += v[k+1].w;
    }
    a0.x += a1.x; a0.y += a1.y; a0.z += a1.z; a0.w += a1.w;
    float local = a0.x * a0.x + a0.y * a0.y + a0.z * a0.z + a0.w * a0.w;

    // ---- block reduce -> partial sum of squares ----
    __shared__ float swarp[8];
    __shared__ unsigned int s_last;
    #pragma unroll
    for (int off = 16; off > 0; off >>= 1)
        local += __shfl_xor_sync(0xFFFFFFFFu, local, off);
    if (lane == 0) swarp[wid] = local;
    __syncthreads();

    // ---- two-level arrival tree (avoids 128-deep single-address atomic queue) ----
    if (tid == 0) {
        float tot = 0.0f;
        #pragma unroll
        for (int w = 0; w < 8; w++) tot += swarp[w];
        g_part[row][slice] = tot;
        __threadfence();
        unsigned int last = 0;
        unsigned int r1 = atomicAdd(&g_cnt1[bid >> 3][0], 1u);  // 8 CTAs per counter
        if (r1 == 7u) {
            unsigned int r2 = atomicAdd(&g_cnt2, 1u);
            last = (r2 == NL1 - 1u) ? 1u : 0u;
        }
        s_last = last;
    }
    __syncthreads();

    // ---- last block finalizes ----
    if (s_last) {
        __threadfence();
        __shared__ float s_rt[2];
        __shared__ float s_bce[2];

        if (tid < 64) {
            float rt = 0.0f;
            if (tid < BB) {
                float sa = __ldcg(&g_part[tid][0])      + __ldcg(&g_part[tid][1]);
                float sn = __ldcg(&g_part[BB + tid][0]) + __ldcg(&g_part[BB + tid][1]);
                float la = fabsf(100.0f - sqrtf(sa) * (1.0f / KK));
                float ln = sqrtf(sn) * (1.0f / KK);
                float l = la + ln;
                rt = l * l;
            }
            // vls = concat([vls_norm, vls_abn]); norm rows are 32..63
            float vv = (tid < BB) ? __ldcg(&g_vls[BB + tid]) : __ldcg(&g_vls[tid - BB]);
            float lab = label[tid];
            float logp   = fmaxf(logf(vv),    -100.0f);
            float log1mp = fmaxf(log1pf(-vv), -100.0f);
            float bce = lab * logp + (1.0f - lab) * log1mp;

            #pragma unroll
            for (int off = 16; off > 0; off >>= 1) {
                rt  += __shfl_xor_sync(0xFFFFFFFFu, rt,  off);
                bce += __shfl_xor_sync(0xFFFFFFFFu, bce, off);
            }
            if (lane == 0) { s_rt[wid] = rt; s_bce[wid] = bce; }
        }
        // reset arrival counters for next graph replay
        if (tid >= 64 && tid < 64 + NL1) g_cnt1[tid - 64][0] = 0u;
        if (tid == 64 + NL1) g_cnt2 = 0u;
        __syncthreads();
        if (tid == 0) {
            out[0] = 1e-4f * ((s_rt[0] + s_rt[1]) * (1.0f / BB));
            out[1] = -(s_bce[0] + s_bce[1]) * (1.0f / 64.0f);
        }
    }
}

extern "C" void kernel_launch(void* const* d_in, const int* in_sizes, int n_in,
                              void* d_out, int out_size)
{
    const float* abnr_fmagn = (const float*)d_in[0];
    const float* norm_fmagn = (const float*)d_in[1];
    const float* abnr_feats = (const float*)d_in[2];
    const float* norm_feats = (const float*)d_in[3];
    const float* abnr_sls   = (const float*)d_in[4];
    const float* norm_sls   = (const float*)d_in[5];
    const float* label      = (const float*)d_in[6];
    const float* drop_abn   = (const float*)d_in[7];
    const float* drop_norm  = (const float*)d_in[8];

    fused_kernel<<<2 * BB * SLICES, NTHR>>>(abnr_fmagn, norm_fmagn,
                                            abnr_feats, norm_feats,
                                            abnr_sls, norm_sls,
                                            drop_abn, drop_norm,
                                            label, (float*)d_out);
}